// round 3
// baseline (speedup 1.0000x reference)
#include <cuda_runtime.h>
#include <cstdint>

// Router: logits = x @ W^T  (T x 2048) @ (2048 x 64)  -> softmax -> top2
// Outputs concatenated fp32: mask[T*64] | idx[T*2] | router_probs[T*64] | probs[T*64]

#define TM 64
#define DK 16
#define THREADS 128
#define WS 72   // padded W smem row stride (floats); k*WS*4 % 16 == 0
#define LS 68   // logits row stride (floats); 68*4=272, 16B-aligned rows

typedef unsigned long long ull;

__device__ __forceinline__ ull dup2(float w) {
    ull r;
    asm("mov.b64 %0, {%1, %1};" : "=l"(r) : "f"(w));
    return r;
}
__device__ __forceinline__ void fma2(ull& d, ull a, ull b) {
    asm("fma.rn.f32x2 %0, %1, %2, %0;" : "+l"(d) : "l"(a), "l"(b));
}

__global__ void __launch_bounds__(THREADS)
router_kernel(const float* __restrict__ x, const float* __restrict__ W,
              float* __restrict__ out, int T)
{
    // tiles: Xs[2][DK][TM] (2048) + Ws[2][DK][WS] (2304) = 4352 floats
    // epilogue reuses the same 4352 floats as logits [TM][LS]
    __shared__ __align__(16) float sm[2 * DK * TM + 2 * DK * WS];

    float* Xs = sm;                    // [2][DK][TM]
    float* Wsm = sm + 2 * DK * TM;     // [2][DK][WS]

    const int tid = threadIdx.x;
    const int tBase = blockIdx.x * TM;

    // ---- global load assignment ----
    const int xtok = tid >> 1;            // 0..63
    const int xko  = (tid & 1) * 8;       // 0 or 8
    const int xrow = tBase + xtok;
    const bool xOK = (xrow < T);
    const float4* xg = reinterpret_cast<const float4*>(x + (size_t)xrow * 2048);

    const int we  = tid >> 1;             // expert 0..63
    const int wko = (tid & 1) * 8;
    const float4* wg = reinterpret_cast<const float4*>(W + (size_t)we * 2048);

    // ---- microtile: 4 tokens x 8 experts (expert-paired f32x2) ----
    const int trow = tid >> 3;   // 0..15 -> tokens trow*4 .. +3
    const int tcol = tid & 7;    // 0..7  -> experts tcol*8 .. +7

    float4 xr[2];
    float4 wr[2];

    ull acc[4][4];   // [token][expert-pair]
#pragma unroll
    for (int t = 0; t < 4; t++)
#pragma unroll
        for (int e = 0; e < 4; e++) acc[t][e] = 0ULL;

    // ---- prologue: load tile 0 ----
    {
        if (xOK) {
            xr[0] = xg[xko / 4 + 0];
            xr[1] = xg[xko / 4 + 1];
        } else {
            xr[0] = xr[1] = make_float4(0.f, 0.f, 0.f, 0.f);
        }
        wr[0] = wg[wko / 4 + 0];
        wr[1] = wg[wko / 4 + 1];

        float* Xb = Xs;
        float* Wb = Wsm;
#pragma unroll
        for (int i = 0; i < 2; i++) {
            Xb[(xko + i * 4 + 0) * TM + xtok] = (&xr[i].x)[0];
            Xb[(xko + i * 4 + 1) * TM + xtok] = (&xr[i].x)[1];
            Xb[(xko + i * 4 + 2) * TM + xtok] = (&xr[i].x)[2];
            Xb[(xko + i * 4 + 3) * TM + xtok] = (&xr[i].x)[3];
            Wb[(wko + i * 4 + 0) * WS + we] = (&wr[i].x)[0];
            Wb[(wko + i * 4 + 1) * WS + we] = (&wr[i].x)[1];
            Wb[(wko + i * 4 + 2) * WS + we] = (&wr[i].x)[2];
            Wb[(wko + i * 4 + 3) * WS + we] = (&wr[i].x)[3];
        }
    }
    __syncthreads();

    const int NKT = 2048 / DK;  // 128 k-tiles

    for (int kt = 0; kt < NKT; kt++) {
        // register prefetch of next tile
        if (kt + 1 < NKT) {
            const int k0 = (kt + 1) * DK;
            if (xOK) {
                xr[0] = xg[(k0 + xko) / 4 + 0];
                xr[1] = xg[(k0 + xko) / 4 + 1];
            }
            wr[0] = wg[(k0 + wko) / 4 + 0];
            wr[1] = wg[(k0 + wko) / 4 + 1];
        }

        // compute on current buffer
        {
            const int buf = kt & 1;
            const float* Xb = Xs + buf * DK * TM;
            const float* Wb = Wsm + buf * DK * WS;
#pragma unroll
            for (int k = 0; k < DK; k++) {
                // 4 tokens via one LDS.128, duplicated to f32x2
                const float4 xv = *reinterpret_cast<const float4*>(Xb + k * TM + trow * 4);
                ull xd[4];
                xd[0] = dup2(xv.x); xd[1] = dup2(xv.y);
                xd[2] = dup2(xv.z); xd[3] = dup2(xv.w);

                // 8 experts as 4 native f32x2 pairs via two LDS.128 (no dup)
                const ulonglong2 wa =
                    *reinterpret_cast<const ulonglong2*>(Wb + k * WS + tcol * 8);
                const ulonglong2 wb =
                    *reinterpret_cast<const ulonglong2*>(Wb + k * WS + tcol * 8 + 4);
                ull wp[4] = {wa.x, wa.y, wb.x, wb.y};

#pragma unroll
                for (int t = 0; t < 4; t++)
#pragma unroll
                    for (int e = 0; e < 4; e++) fma2(acc[t][e], xd[t], wp[e]);
            }
        }

        // stage next tile
        if (kt + 1 < NKT) {
            const int buf = (kt + 1) & 1;
            float* Xb = Xs + buf * DK * TM;
            float* Wb = Wsm + buf * DK * WS;
#pragma unroll
            for (int i = 0; i < 2; i++) {
                Xb[(xko + i * 4 + 0) * TM + xtok] = (&xr[i].x)[0];
                Xb[(xko + i * 4 + 1) * TM + xtok] = (&xr[i].x)[1];
                Xb[(xko + i * 4 + 2) * TM + xtok] = (&xr[i].x)[2];
                Xb[(xko + i * 4 + 3) * TM + xtok] = (&xr[i].x)[3];
                Wb[(wko + i * 4 + 0) * WS + we] = (&wr[i].x)[0];
                Wb[(wko + i * 4 + 1) * WS + we] = (&wr[i].x)[1];
                Wb[(wko + i * 4 + 2) * WS + we] = (&wr[i].x)[2];
                Wb[(wko + i * 4 + 3) * WS + we] = (&wr[i].x)[3];
            }
        }
        __syncthreads();
    }

    // ---- dump logits to smem [TM][LS]; expert pairs store as 8B words ----
    float* lg = sm;
#pragma unroll
    for (int t = 0; t < 4; t++) {
        const int token = trow * 4 + t;
#pragma unroll
        for (int e = 0; e < 4; e++) {
            *reinterpret_cast<ull*>(lg + token * LS + tcol * 8 + e * 2) = acc[t][e];
        }
    }
    __syncthreads();

    // ---- epilogue: one thread = one token (threads 0..63) ----
    if (tid >= TM) return;
    const int row = tBase + tid;
    if (row >= T) return;

    float l[64];
#pragma unroll
    for (int e = 0; e < 64; e += 4) {
        const float4 v = *reinterpret_cast<const float4*>(lg + tid * LS + e);
        l[e] = v.x; l[e + 1] = v.y; l[e + 2] = v.z; l[e + 3] = v.w;
    }

    // top-2 on logits (earliest index wins ties, matching lax.top_k)
    float m1 = -3.402823466e38f, m2 = -3.402823466e38f;
    int i1 = 0, i2 = 0;
#pragma unroll
    for (int e = 0; e < 64; e++) {
        const float v = l[e];
        if (v > m1) { m2 = m1; i2 = i1; m1 = v; i1 = e; }
        else if (v > m2) { m2 = v; i2 = e; }
    }

    // softmax
    float s = 0.f;
    float p[64];
#pragma unroll
    for (int e = 0; e < 64; e++) {
        p[e] = __expf(l[e] - m1);
        s += p[e];
    }
    const float inv = 1.0f / s;

    const float p1 = p[i1] * inv;
    const float p2 = p[i2] * inv;
    const float rs = 1.0f / (p1 + p2);

    // output layout (all fp32): mask | idx | router_probs | probs
    const size_t Tz = (size_t)T;
    float* mask = out;
    float* idxo = out + Tz * 64;
    float* rp   = out + Tz * 64 + Tz * 2;
    float* pr   = out + Tz * 64 + Tz * 2 + Tz * 64;
    const size_t gt = (size_t)row;

#pragma unroll
    for (int e = 0; e < 64; e++) {
        const float pv = p[e] * inv;
        const bool sel = (e == i1) | (e == i2);
        pr[gt * 64 + e]   = pv;
        mask[gt * 64 + e] = sel ? 1.0f : 0.0f;
        rp[gt * 64 + e]   = sel ? pv * rs : 0.0f;
    }
    idxo[gt * 2 + 0] = (float)i1;
    idxo[gt * 2 + 1] = (float)i2;
}

extern "C" void kernel_launch(void* const* d_in, const int* in_sizes, int n_in,
                              void* d_out, int out_size)
{
    const float* x = (const float*)d_in[0];
    const float* W = (const float*)d_in[1];
    const int T = in_sizes[0] / 2048;
    const int blocks = (T + TM - 1) / TM;
    router_kernel<<<blocks, THREADS>>>(x, W, (float*)d_out, T);
}

// round 5
// speedup vs baseline: 4.3106x; 4.3106x over previous
#include <cuda_runtime.h>
#include <cstdint>

// Router: logits = x @ W^T via split-bf16 mma.sync (3 terms), fused softmax/top-2.
// Outputs concatenated fp32: mask[T*64] | idx[T*2] | router_probs[T*64] | probs[T*64]

#define THREADS 256
#define TM 128            // tokens per CTA
#define CK 64             // K chunk
#define NCH (2048 / CK)   // 32
#define ASTR 144          // smem row stride bytes (64 bf16 = 128B + 16 pad)

// per-buffer smem layout (bytes)
#define AHI_O 0
#define ALO_O 18432       // 128*144
#define BHI_O 36864
#define BLO_O 46080       // +64*144
#define BUFSZ 55296
#define SMEMB (2 * BUFSZ)
#define LS 68             // logits row stride (floats), 272B rows (16B aligned)

__device__ __forceinline__ uint32_t smem_u32(const void* p) {
    uint32_t a;
    asm("{ .reg .u64 t; cvta.to.shared.u64 t, %1; cvt.u32.u64 %0, t; }"
        : "=r"(a) : "l"(p));
    return a;
}

__device__ __forceinline__ void ldm4(uint32_t* r, uint32_t addr) {
    asm volatile("ldmatrix.sync.aligned.m8n8.x4.shared.b16 {%0,%1,%2,%3}, [%4];"
        : "=r"(r[0]), "=r"(r[1]), "=r"(r[2]), "=r"(r[3]) : "r"(addr));
}

__device__ __forceinline__ void mma16816(float* d, const uint32_t* a,
                                         uint32_t b0, uint32_t b1) {
    asm volatile("mma.sync.aligned.m16n8k16.row.col.f32.bf16.bf16.f32 "
        "{%0,%1,%2,%3}, {%4,%5,%6,%7}, {%8,%9}, {%0,%1,%2,%3};"
        : "+f"(d[0]), "+f"(d[1]), "+f"(d[2]), "+f"(d[3])
        : "r"(a[0]), "r"(a[1]), "r"(a[2]), "r"(a[3]), "r"(b0), "r"(b1));
}

// fp32x4 -> bf16 hi x4 (8B) + bf16 lo x4 (8B)
__device__ __forceinline__ void cvt_store(uint32_t hi_addr, uint32_t lo_addr, float4 v) {
    uint32_t hu0, hu1;
    asm("cvt.rn.bf16x2.f32 %0, %1, %2;" : "=r"(hu0) : "f"(v.y), "f"(v.x));
    asm("cvt.rn.bf16x2.f32 %0, %1, %2;" : "=r"(hu1) : "f"(v.w), "f"(v.z));
    const float h0 = __uint_as_float(hu0 << 16);
    const float h1 = __uint_as_float(hu0 & 0xffff0000u);
    const float h2 = __uint_as_float(hu1 << 16);
    const float h3 = __uint_as_float(hu1 & 0xffff0000u);
    uint32_t gu0, gu1;
    asm("cvt.rn.bf16x2.f32 %0, %1, %2;" : "=r"(gu0) : "f"(v.y - h1), "f"(v.x - h0));
    asm("cvt.rn.bf16x2.f32 %0, %1, %2;" : "=r"(gu1) : "f"(v.w - h3), "f"(v.z - h2));
    uint64_t H, L;
    asm("mov.b64 %0, {%1, %2};" : "=l"(H) : "r"(hu0), "r"(hu1));
    asm("mov.b64 %0, {%1, %2};" : "=l"(L) : "r"(gu0), "r"(gu1));
    asm volatile("st.shared.b64 [%0], %1;" :: "r"(hi_addr), "l"(H) : "memory");
    asm volatile("st.shared.b64 [%0], %1;" :: "r"(lo_addr), "l"(L) : "memory");
}

__global__ void __launch_bounds__(THREADS, 1)
router_kernel(const float* __restrict__ x, const float* __restrict__ W,
              float* __restrict__ out, int T)
{
    extern __shared__ __align__(128) char dsm[];
    const uint32_t sb = smem_u32(dsm);

    const int tid = threadIdx.x;
    const int wid = tid >> 5;
    const int lane = tid & 31;
    const int row0 = blockIdx.x * TM;

    // global load coords: thread covers rows i*16 + lr, float4-col lc
    const int lr = tid >> 4;    // 0..15
    const int lc = tid & 15;    // 0..15

    float4 ax[8], bw[4];
    float d[8][4];
#pragma unroll
    for (int t = 0; t < 8; t++)
#pragma unroll
        for (int j = 0; j < 4; j++) d[t][j] = 0.f;

    // ---- prologue: chunk 0 load + convert/store to buf0 ----
#pragma unroll
    for (int i = 0; i < 8; i++) {
        const int grow = row0 + i * 16 + lr;
        ax[i] = (grow < T)
            ? *reinterpret_cast<const float4*>(x + (size_t)grow * 2048 + lc * 4)
            : make_float4(0.f, 0.f, 0.f, 0.f);
    }
#pragma unroll
    for (int i = 0; i < 4; i++)
        bw[i] = *reinterpret_cast<const float4*>(W + (size_t)(i * 16 + lr) * 2048 + lc * 4);
    {
        const uint32_t tb = sb;
#pragma unroll
        for (int i = 0; i < 8; i++) {
            const uint32_t o = (uint32_t)((i * 16 + lr) * ASTR + lc * 8);
            cvt_store(tb + AHI_O + o, tb + ALO_O + o, ax[i]);
        }
#pragma unroll
        for (int i = 0; i < 4; i++) {
            const uint32_t o = (uint32_t)((i * 16 + lr) * ASTR + lc * 8);
            cvt_store(tb + BHI_O + o, tb + BLO_O + o, bw[i]);
        }
    }
    __syncthreads();

    // ldmatrix per-lane offsets
    const uint32_t a_off = (uint32_t)((wid * 16 + (lane & 15)) * ASTR + ((lane >> 4) << 4));
    const uint32_t b_off = (uint32_t)((((lane & 7) + ((lane >> 4) & 1) * 8)) * ASTR
                                      + (((lane >> 3) & 1) << 4));

    for (int c = 0; c < NCH; c++) {
        // register prefetch of next chunk
        if (c + 1 < NCH) {
            const int k0 = (c + 1) * CK;
#pragma unroll
            for (int i = 0; i < 8; i++) {
                const int grow = row0 + i * 16 + lr;
                if (grow < T)
                    ax[i] = *reinterpret_cast<const float4*>(
                        x + (size_t)grow * 2048 + k0 + lc * 4);
            }
#pragma unroll
            for (int i = 0; i < 4; i++)
                bw[i] = *reinterpret_cast<const float4*>(
                    W + (size_t)(i * 16 + lr) * 2048 + k0 + lc * 4);
        }

        // ---- compute on current buffer ----
        {
            const uint32_t tb = sb + (uint32_t)(c & 1) * BUFSZ;
#pragma unroll
            for (int kk = 0; kk < 4; kk++) {
                const uint32_t ko = kk * 32;  // 16 bf16 = 32 bytes
                uint32_t ah[4], al[4];
                ldm4(ah, tb + AHI_O + a_off + ko);
                ldm4(al, tb + ALO_O + a_off + ko);
#pragma unroll
                for (int j = 0; j < 4; j++) {
                    uint32_t bh[4], bl[4];
                    const uint32_t bo = (uint32_t)(j * 16 * ASTR) + b_off + ko;
                    ldm4(bh, tb + BHI_O + bo);
                    ldm4(bl, tb + BLO_O + bo);
#pragma unroll
                    for (int tt = 0; tt < 2; tt++) {
                        float* dd = d[j * 2 + tt];
                        mma16816(dd, ah, bh[tt * 2], bh[tt * 2 + 1]);
                        mma16816(dd, ah, bl[tt * 2], bl[tt * 2 + 1]);
                        mma16816(dd, al, bh[tt * 2], bh[tt * 2 + 1]);
                    }
                }
            }
        }

        // ---- convert + store next chunk into other buffer ----
        if (c + 1 < NCH) {
            const uint32_t tb = sb + (uint32_t)((c + 1) & 1) * BUFSZ;
#pragma unroll
            for (int i = 0; i < 8; i++) {
                const uint32_t o = (uint32_t)((i * 16 + lr) * ASTR + lc * 8);
                cvt_store(tb + AHI_O + o, tb + ALO_O + o, ax[i]);
            }
#pragma unroll
            for (int i = 0; i < 4; i++) {
                const uint32_t o = (uint32_t)((i * 16 + lr) * ASTR + lc * 8);
                cvt_store(tb + BHI_O + o, tb + BLO_O + o, bw[i]);
            }
        }
        __syncthreads();
    }

    // ---- dump logits to smem [TM][LS] (reuses buf0 region) ----
    float* lg = reinterpret_cast<float*>(dsm);
    {
        const int r1 = wid * 16 + (lane >> 2);
        const int n0 = (lane & 3) * 2;
#pragma unroll
        for (int t = 0; t < 8; t++) {
            *reinterpret_cast<float2*>(lg + r1 * LS + t * 8 + n0) =
                make_float2(d[t][0], d[t][1]);
            *reinterpret_cast<float2*>(lg + (r1 + 8) * LS + t * 8 + n0) =
                make_float2(d[t][2], d[t][3]);
        }
    }
    __syncthreads();

    // ---- epilogue: one thread = one token (threads 0..127) ----
    if (tid >= TM) return;
    const int row = row0 + tid;
    if (row >= T) return;

    float l[64];
#pragma unroll
    for (int e = 0; e < 64; e += 4) {
        const float4 v = *reinterpret_cast<const float4*>(lg + tid * LS + e);
        l[e] = v.x; l[e + 1] = v.y; l[e + 2] = v.z; l[e + 3] = v.w;
    }

    // top-2 (earliest index wins ties, matching lax.top_k)
    float m1 = -3.402823466e38f, m2 = -3.402823466e38f;
    int i1 = 0, i2 = 0;
#pragma unroll
    for (int e = 0; e < 64; e++) {
        const float v = l[e];
        if (v > m1) { m2 = m1; i2 = i1; m1 = v; i1 = e; }
        else if (v > m2) { m2 = v; i2 = e; }
    }

    float s = 0.f;
    float p[64];
#pragma unroll
    for (int e = 0; e < 64; e++) {
        p[e] = __expf(l[e] - m1);
        s += p[e];
    }
    const float inv = 1.0f / s;

    const float p1 = p[i1] * inv;
    const float p2 = p[i2] * inv;
    const float rs = 1.0f / (p1 + p2);

    const size_t Tz = (size_t)T;
    float* mask = out;
    float* idxo = out + Tz * 64;
    float* rp   = out + Tz * 64 + Tz * 2;
    float* pr   = out + Tz * 64 + Tz * 2 + Tz * 64;
    const size_t gt = (size_t)row;

#pragma unroll
    for (int e = 0; e < 64; e += 4) {
        float4 pv4, m4, r4;
        float* pvp = &pv4.x; float* mp = &m4.x; float* rpp = &r4.x;
#pragma unroll
        for (int j = 0; j < 4; j++) {
            const int ee = e + j;
            const float pv = p[ee] * inv;
            const bool sel = (ee == i1) | (ee == i2);
            pvp[j] = pv;
            mp[j] = sel ? 1.0f : 0.0f;
            rpp[j] = sel ? pv * rs : 0.0f;
        }
        *reinterpret_cast<float4*>(pr + gt * 64 + e) = pv4;
        *reinterpret_cast<float4*>(mask + gt * 64 + e) = m4;
        *reinterpret_cast<float4*>(rp + gt * 64 + e) = r4;
    }
    idxo[gt * 2 + 0] = (float)i1;
    idxo[gt * 2 + 1] = (float)i2;
}

extern "C" void kernel_launch(void* const* d_in, const int* in_sizes, int n_in,
                              void* d_out, int out_size)
{
    const float* x = (const float*)d_in[0];
    const float* W = (const float*)d_in[1];
    const int T = in_sizes[0] / 2048;
    cudaFuncSetAttribute(router_kernel,
                         cudaFuncAttributeMaxDynamicSharedMemorySize, SMEMB);
    const int blocks = (T + TM - 1) / TM;
    router_kernel<<<blocks, THREADS, SMEMB>>>(x, W, (float*)d_out, T);
}